// round 7
// baseline (speedup 1.0000x reference)
#include <cuda_runtime.h>
#include <cstddef>

namespace {
constexpr int Bsz = 512, Tsz = 1024, Hs = 64, R = 4;
constexpr int QS = 20;            // quarter stride (floats): conflict-free, 16B-aligned
constexpr int RS = 4 * QS;        // row stride
}

using ull = unsigned long long;

__device__ __forceinline__ void unpack2(ull v, float& lo, float& hi) {
    asm("mov.b64 {%0,%1},%2;" : "=f"(lo), "=f"(hi) : "l"(v));
}
__device__ __forceinline__ ull ffma2(ull a, ull b, ull c) {
    ull d;
    asm("fma.rn.f32x2 %0,%1,%2,%3;" : "=l"(d) : "l"(a), "l"(b), "l"(c));
    return d;
}
__device__ __forceinline__ float fast_ex2(float x) {
    float r; asm("ex2.approx.f32 %0,%1;" : "=f"(r) : "f"(x)); return r;
}
__device__ __forceinline__ float fast_rcp(float x) {
    float r; asm("rcp.approx.f32 %0,%1;" : "=f"(r) : "f"(x)); return r;
}
__device__ __forceinline__ float fsigmoid(float x) {
    return fast_rcp(1.0f + fast_ex2(-1.44269504f * x));
}
__device__ __forceinline__ float ftanh(float x) {
    float ax = fabsf(x);
    float t  = fast_ex2(-2.88539008f * ax);          // exp(-2|x|)
    float y  = (1.0f - t) * fast_rcp(1.0f + t);
    return copysignf(y, x);
}
__device__ __forceinline__ int hidx(int j) {         // k index -> padded offset
    return (j >> 4) * QS + (j & 15);
}

// ---------------------------------------------------------------------------
// Fused 2-layer GRU. Grid 128 x 768; CTA owns 4 batch rows.
// PHASE A: thread = (m = tx>>8, j = (tx&255)>>2, q = tx&3). Each thread dots
//   3 gate-rows (j, j+64, j+128) of matrix m over its 16-k quarter against 4
//   rows (m=0: Whh0.h1[s-1], m=1: Wih1.h1[s-1], m=2: Whh1.h2[s-2]).
//   24 packed f32x2 weight regs (48 regs -> fits 84-reg cap at 768 thr).
//   2-level shfl (xor1, xor2) completes dots; q==0 lanes post (+biases) to
//   sh_p[m][gate][row][j].
// PHASE B: 512 combine tasks map 1:1 to threads 0..511 (L=tx>>8, r, j).
//   L0 tasks apply the x-projection with weights read from smem (sh_wx).
//   m=2 threads stage x[s+1]. Two barriers/step, Tsz+1 steps, no scratch.
// ---------------------------------------------------------------------------
__global__ void __launch_bounds__(768, 1) gru_fused(
    const float* __restrict__ x,
    const float* __restrict__ W_ih0, const float* __restrict__ W_hh0,
    const float* __restrict__ b_ih0, const float* __restrict__ b_hh0,
    const float* __restrict__ W_ih1, const float* __restrict__ W_hh1,
    const float* __restrict__ b_ih1, const float* __restrict__ b_hh1,
    float* __restrict__ outp,        // (B,T,64)
    float* __restrict__ finalp)      // (B,64)
{
    __shared__ float sh_h1[2][R * RS];    // [parity][row*RS + hidx(k)]
    __shared__ float sh_h2[2][R * RS];
    __shared__ float sh_p [3][3][R][64];  // [matrix][gate][row][j]
    __shared__ float sh_wx[10][64];       // W_ih0 rows (9) + b_ih0 n-part (1)
    __shared__ float sh_x [2][R][3];      // staged x[t]

    const int tx = threadIdx.x;
    const int m  = tx >> 8;               // 0: Whh0, 1: Wih1, 2: Whh1
    const int l8 = tx & 255;
    const int j  = l8 >> 2;               // 0..63
    const int q  = l8 & 3;                // k-quarter
    const int kb = q * 16;

    // ---- phase-A weights: 3 gate-rows x 16-k-quarter, packed f32x2 ----
    const float* __restrict__ Wm = (m == 0) ? W_hh0 : (m == 1) ? W_ih1 : W_hh1;
    ull w2[24];
    const ull* __restrict__ Wll = reinterpret_cast<const ull*>(Wm);
#pragma unroll
    for (int g3 = 0; g3 < 3; g3++) {
        const int g = j + g3 * 64;
#pragma unroll
        for (int kk = 0; kk < 8; kk++)
            w2[g3 * 8 + kk] = Wll[(g * 64 + kb) / 2 + kk];
    }

    // folded biases (posted with the dots by q==0 lanes)
    float badd0 = 0.f, badd1 = 0.f, badd2 = 0.f;
    if (m == 0) {
        badd0 = b_ih0[j]       + b_hh0[j];
        badd1 = b_ih0[j + 64]  + b_hh0[j + 64];
        badd2 = b_hh0[j + 128];                  // recurrent n (inside r*)
    } else if (m == 1) {
        badd0 = b_ih1[j]       + b_hh1[j];
        badd1 = b_ih1[j + 64]  + b_hh1[j + 64];
        badd2 = b_ih1[j + 128];                  // input n
    } else {
        badd2 = b_hh1[j + 128];                  // recurrent n
    }

    // ---- phase-B task (threads 0..511): (L = tx>>8, r, jj) ----
    const int L  = tx >> 8;                // 0 or 1 for task threads
    const int rB = (tx >> 6) & 3;
    const int jB = tx & 63;

    // x staging: m==2 threads 0..11
    const int  sx  = tx - 512;
    const bool xst = (m == 2) && (sx < 12);
    const int  xr  = xst ? sx / 3 : 0, xc = xst ? sx % 3 : 0;
    const int row4 = blockIdx.x * 4;

    // ---- init ----
    for (int i = tx; i < 2 * R * RS; i += 768) {
        reinterpret_cast<float*>(sh_h1)[i] = 0.f;
        reinterpret_cast<float*>(sh_h2)[i] = 0.f;
    }
    for (int i = tx; i < 640; i += 768) {
        const int rw = i >> 6, cl = i & 63;
        sh_wx[rw][cl] = (rw < 9)
            ? W_ih0[((rw / 3) * 64 + cl) * 3 + (rw % 3)]
            : b_ih0[cl + 128];
    }
    if (xst)
        sh_x[0][xr][xc] = __ldg(&x[((size_t)(row4 + xr) * Tsz) * 3 + xc]);
    __syncthreads();

    for (int s = 0; s <= Tsz; s++) {
        const int par = s & 1;

        // ===================== PHASE A: dots =============================
        const float* __restrict__ hsrc =
            (m == 2) ? &sh_h2[par][0] : &sh_h1[par][0];
#pragma unroll
        for (int r = 0; r < R; r++) {
            const ulonglong2* __restrict__ hb =
                reinterpret_cast<const ulonglong2*>(hsrc + r * RS + q * QS);
            ull a0 = 0ull, a1 = 0ull, a2 = 0ull;
#pragma unroll
            for (int i = 0; i < 4; i++) {
                const ulonglong2 h4 = hb[i];               // LDS.128, bcast
                a0 = ffma2(h4.x, w2[2 * i],          a0);
                a0 = ffma2(h4.y, w2[2 * i + 1],      a0);
                a1 = ffma2(h4.x, w2[8 + 2 * i],      a1);
                a1 = ffma2(h4.y, w2[8 + 2 * i + 1],  a1);
                a2 = ffma2(h4.x, w2[16 + 2 * i],     a2);
                a2 = ffma2(h4.y, w2[16 + 2 * i + 1], a2);
            }
            float l, h;
            unpack2(a0, l, h); float pr = l + h;
            unpack2(a1, l, h); float pz = l + h;
            unpack2(a2, l, h); float pn = l + h;
            pr += __shfl_xor_sync(0xffffffffu, pr, 1);
            pz += __shfl_xor_sync(0xffffffffu, pz, 1);
            pn += __shfl_xor_sync(0xffffffffu, pn, 1);
            pr += __shfl_xor_sync(0xffffffffu, pr, 2);
            pz += __shfl_xor_sync(0xffffffffu, pz, 2);
            pn += __shfl_xor_sync(0xffffffffu, pn, 2);
            if (q == 0) {
                sh_p[m][0][r][j] = pr + badd0;
                sh_p[m][1][r][j] = pz + badd1;
                sh_p[m][2][r][j] = pn + badd2;
            }
        }
        __syncthreads();

        // ===================== PHASE B: combines ==========================
        if (m < 2) {                               // 512 tasks, 1:1
            if (L == 0) {
                if (s < Tsz) {                     // h1[s]
                    const float x0 = sh_x[par][rB][0];
                    const float x1 = sh_x[par][rB][1];
                    const float x2 = sh_x[par][rB][2];
                    const float ar = sh_p[0][0][rB][jB]
                        + fmaf(x2, sh_wx[2][jB],
                          fmaf(x1, sh_wx[1][jB], x0 * sh_wx[0][jB]));
                    const float az = sh_p[0][1][rB][jB]
                        + fmaf(x2, sh_wx[5][jB],
                          fmaf(x1, sh_wx[4][jB], x0 * sh_wx[3][jB]));
                    const float xan = sh_wx[9][jB]
                        + fmaf(x2, sh_wx[8][jB],
                          fmaf(x1, sh_wx[7][jB], x0 * sh_wx[6][jB]));
                    const float rr = fsigmoid(ar);
                    const float zz = fsigmoid(az);
                    const float nn = ftanh(fmaf(rr, sh_p[0][2][rB][jB], xan));
                    const float hp = sh_h1[par][rB * RS + hidx(jB)];
                    sh_h1[par ^ 1][rB * RS + hidx(jB)] = fmaf(zz, hp - nn, nn);
                }
            } else {
                if (s >= 1) {                      // h2[s-1] -> output
                    const int tau = s - 1;
                    const float ar = sh_p[1][0][rB][jB] + sh_p[2][0][rB][jB];
                    const float az = sh_p[1][1][rB][jB] + sh_p[2][1][rB][jB];
                    const float rr = fsigmoid(ar);
                    const float zz = fsigmoid(az);
                    const float nn = ftanh(fmaf(rr, sh_p[2][2][rB][jB],
                                                    sh_p[1][2][rB][jB]));
                    const float hp = sh_h2[par][rB * RS + hidx(jB)];
                    const float hn = fmaf(zz, hp - nn, nn);
                    sh_h2[par ^ 1][rB * RS + hidx(jB)] = hn;
                    outp[((size_t)(row4 + rB) * Tsz + tau) * Hs + jB] = hn;
                    if (tau == Tsz - 1)
                        finalp[(row4 + rB) * Hs + jB] = hn;
                }
            }
        } else if (xst && s + 1 < Tsz) {
            // stage x[s+1] into parity (s+1)&1
            sh_x[par ^ 1][xr][xc] =
                __ldg(&x[((size_t)(row4 + xr) * Tsz + (s + 1)) * 3 + xc]);
        }
        __syncthreads();
    }
}

// ---------------------------------------------------------------------------
extern "C" void kernel_launch(void* const* d_in, const int* in_sizes, int n_in,
                              void* d_out, int out_size)
{
    (void)in_sizes; (void)n_in; (void)out_size;
    const float* x     = (const float*)d_in[0];
    const float* W_ih0 = (const float*)d_in[1];
    const float* W_hh0 = (const float*)d_in[2];
    const float* b_ih0 = (const float*)d_in[3];
    const float* b_hh0 = (const float*)d_in[4];
    const float* W_ih1 = (const float*)d_in[5];
    const float* W_hh1 = (const float*)d_in[6];
    const float* b_ih1 = (const float*)d_in[7];
    const float* b_hh1 = (const float*)d_in[8];

    float* out    = (float*)d_out;
    float* finalh = out + (size_t)Bsz * Tsz * Hs;

    gru_fused<<<128, 768>>>(x, W_ih0, W_hh0, b_ih0, b_hh0,
                            W_ih1, W_hh1, b_ih1, b_hh1, out, finalh);
}

// round 8
// speedup vs baseline: 1.1415x; 1.1415x over previous
#include <cuda_runtime.h>
#include <cstddef>

namespace {
constexpr int Bsz = 512, Tsz = 1024, Hs = 64, R = 4;
constexpr int QS = 20;            // quarter stride (floats): bank-spread, 16B-aligned
constexpr int RS = 4 * QS;        // row stride (80 floats)
}

using ull = unsigned long long;

__device__ __forceinline__ void unpack2(ull v, float& lo, float& hi) {
    asm("mov.b64 {%0,%1},%2;" : "=f"(lo), "=f"(hi) : "l"(v));
}
__device__ __forceinline__ ull ffma2(ull a, ull b, ull c) {
    ull d;
    asm("fma.rn.f32x2 %0,%1,%2,%3;" : "=l"(d) : "l"(a), "l"(b), "l"(c));
    return d;
}
__device__ __forceinline__ float fast_ex2(float x) {
    float r; asm("ex2.approx.f32 %0,%1;" : "=f"(r) : "f"(x)); return r;
}
__device__ __forceinline__ float fast_rcp(float x) {
    float r; asm("rcp.approx.f32 %0,%1;" : "=f"(r) : "f"(x)); return r;
}
__device__ __forceinline__ float fsigmoid(float x) {
    return fast_rcp(1.0f + fast_ex2(-1.44269504f * x));
}
__device__ __forceinline__ float ftanh(float x) {
    float ax = fabsf(x);
    float t  = fast_ex2(-2.88539008f * ax);          // exp(-2|x|)
    float y  = (1.0f - t) * fast_rcp(1.0f + t);
    return copysignf(y, x);
}
__device__ __forceinline__ int hidx(int k) {         // k index -> padded offset
    return (k >> 4) * QS + (k & 15);
}
__device__ __forceinline__ float sum4(const float4& v) {
    return (v.x + v.y) + (v.z + v.w);
}

// ---------------------------------------------------------------------------
// Fused 2-layer GRU. Grid 128 x 768; CTA owns 4 batch rows.
// PHASE A: thread = (m = tx>>8, j = (tx&255)>>2, q = tx&3). Each thread dots
//   3 gate-rows (j, j+64, j+128) of matrix m over its 16-k quarter against 4
//   rows (m=0: Whh0.h1[s-1], m=1: Wih1.h1[s-1], m=2: Whh1.h2[s-2]).
//   NO shuffles: per-quarter partials go straight to sh_p[m][gate][r][j][q]
//   via coalesced STS (fire-and-forget; BAR.SYNC drains STS). q==0 lanes fold
//   the biases into their partial.
// PHASE B: 512 combine tasks 1:1 on threads 0..511; each gate's 4 quarters
//   are read back as ONE LDS.128 and summed. L0 tasks apply the x-projection
//   (weights from smem). m=2 threads stage x[s+1]. Two barriers/step.
// ---------------------------------------------------------------------------
__global__ void __launch_bounds__(768, 1) gru_fused(
    const float* __restrict__ x,
    const float* __restrict__ W_ih0, const float* __restrict__ W_hh0,
    const float* __restrict__ b_ih0, const float* __restrict__ b_hh0,
    const float* __restrict__ W_ih1, const float* __restrict__ W_hh1,
    const float* __restrict__ b_ih1, const float* __restrict__ b_hh1,
    float* __restrict__ outp,        // (B,T,64)
    float* __restrict__ finalp)      // (B,64)
{
    __shared__ float sh_h1[2][R * RS];        // [parity][row*RS + hidx(k)]
    __shared__ float sh_h2[2][R * RS];
    __shared__ float sh_p [3][3][R][64][4];   // [matrix][gate][row][j][quarter]
    __shared__ float sh_wx[10][64];           // W_ih0 rows (9) + b_ih0 n (1)
    __shared__ float sh_x [2][R][3];          // staged x[t]

    const int tx = threadIdx.x;
    const int m  = tx >> 8;               // 0: Whh0, 1: Wih1, 2: Whh1
    const int l8 = tx & 255;
    const int j  = l8 >> 2;               // 0..63
    const int q  = l8 & 3;                // k-quarter
    const int kb = q * 16;

    // ---- phase-A weights: 3 gate-rows x 16-k quarter, packed f32x2 ----
    const float* __restrict__ Wm = (m == 0) ? W_hh0 : (m == 1) ? W_ih1 : W_hh1;
    ull w2[24];
    const ull* __restrict__ Wll = reinterpret_cast<const ull*>(Wm);
#pragma unroll
    for (int g3 = 0; g3 < 3; g3++) {
        const int g = j + g3 * 64;
#pragma unroll
        for (int kk = 0; kk < 8; kk++)
            w2[g3 * 8 + kk] = Wll[(g * 64 + kb) / 2 + kk];
    }

    // biases folded by the q==0 lane only (zero for other quarters)
    float b0q = 0.f, b1q = 0.f, b2q = 0.f;
    if (q == 0) {
        if (m == 0) {
            b0q = b_ih0[j]       + b_hh0[j];
            b1q = b_ih0[j + 64]  + b_hh0[j + 64];
            b2q = b_hh0[j + 128];                // recurrent n (inside r*)
        } else if (m == 1) {
            b0q = b_ih1[j]       + b_hh1[j];
            b1q = b_ih1[j + 64]  + b_hh1[j + 64];
            b2q = b_ih1[j + 128];                // input n
        } else {
            b2q = b_hh1[j + 128];                // recurrent n
        }
    }

    // ---- phase-B task (threads 0..511): (L = tx>>8, rB, jB) ----
    const int L  = tx >> 8;
    const int rB = (tx >> 6) & 3;
    const int jB = tx & 63;

    // x staging: m==2 threads 0..11
    const int  sx  = tx - 512;
    const bool xst = (m == 2) && (sx < 12);
    const int  xr  = xst ? sx / 3 : 0, xc = xst ? sx % 3 : 0;
    const int row4 = blockIdx.x * 4;

    // ---- init ----
    for (int i = tx; i < 2 * R * RS; i += 768) {
        reinterpret_cast<float*>(sh_h1)[i] = 0.f;
        reinterpret_cast<float*>(sh_h2)[i] = 0.f;
    }
    for (int i = tx; i < 640; i += 768) {
        const int rw = i >> 6, cl = i & 63;
        sh_wx[rw][cl] = (rw < 9)
            ? W_ih0[((rw / 3) * 64 + cl) * 3 + (rw % 3)]
            : b_ih0[cl + 128];
    }
    if (xst)
        sh_x[0][xr][xc] = __ldg(&x[((size_t)(row4 + xr) * Tsz) * 3 + xc]);
    __syncthreads();

    for (int s = 0; s <= Tsz; s++) {
        const int par = s & 1;

        // ===================== PHASE A: dots (pure stream) ===============
        const float* __restrict__ hsrc =
            (m == 2) ? &sh_h2[par][0] : &sh_h1[par][0];
#pragma unroll
        for (int r = 0; r < R; r++) {
            const ulonglong2* __restrict__ hb =
                reinterpret_cast<const ulonglong2*>(hsrc + r * RS + q * QS);
            ull a0 = 0ull, a1 = 0ull, a2 = 0ull;
#pragma unroll
            for (int i = 0; i < 4; i++) {
                const ulonglong2 h4 = hb[i];               // LDS.128
                a0 = ffma2(h4.x, w2[2 * i],          a0);
                a0 = ffma2(h4.y, w2[2 * i + 1],      a0);
                a1 = ffma2(h4.x, w2[8 + 2 * i],      a1);
                a1 = ffma2(h4.y, w2[8 + 2 * i + 1],  a1);
                a2 = ffma2(h4.x, w2[16 + 2 * i],     a2);
                a2 = ffma2(h4.y, w2[16 + 2 * i + 1], a2);
            }
            float l, h;
            unpack2(a0, l, h); sh_p[m][0][r][j][q] = (l + h) + b0q;
            unpack2(a1, l, h); sh_p[m][1][r][j][q] = (l + h) + b1q;
            unpack2(a2, l, h); sh_p[m][2][r][j][q] = (l + h) + b2q;
        }
        __syncthreads();                     // drains the STS above

        // ===================== PHASE B: combines ==========================
        if (m < 2) {                          // 512 tasks, 1:1
            if (L == 0) {
                if (s < Tsz) {                // h1[s]
                    const float pr = sum4(*reinterpret_cast<const float4*>(
                        &sh_p[0][0][rB][jB][0]));
                    const float pz = sum4(*reinterpret_cast<const float4*>(
                        &sh_p[0][1][rB][jB][0]));
                    const float pn = sum4(*reinterpret_cast<const float4*>(
                        &sh_p[0][2][rB][jB][0]));
                    const float x0 = sh_x[par][rB][0];
                    const float x1 = sh_x[par][rB][1];
                    const float x2 = sh_x[par][rB][2];
                    const float ar = pr
                        + fmaf(x2, sh_wx[2][jB],
                          fmaf(x1, sh_wx[1][jB], x0 * sh_wx[0][jB]));
                    const float az = pz
                        + fmaf(x2, sh_wx[5][jB],
                          fmaf(x1, sh_wx[4][jB], x0 * sh_wx[3][jB]));
                    const float xan = sh_wx[9][jB]
                        + fmaf(x2, sh_wx[8][jB],
                          fmaf(x1, sh_wx[7][jB], x0 * sh_wx[6][jB]));
                    const float rr = fsigmoid(ar);
                    const float zz = fsigmoid(az);
                    const float nn = ftanh(fmaf(rr, pn, xan));
                    const float hp = sh_h1[par][rB * RS + hidx(jB)];
                    sh_h1[par ^ 1][rB * RS + hidx(jB)] = fmaf(zz, hp - nn, nn);
                }
            } else {
                if (s >= 1) {                 // h2[s-1] -> output
                    const int tau = s - 1;
                    const float ar = sum4(*reinterpret_cast<const float4*>(
                                        &sh_p[1][0][rB][jB][0]))
                                   + sum4(*reinterpret_cast<const float4*>(
                                        &sh_p[2][0][rB][jB][0]));
                    const float az = sum4(*reinterpret_cast<const float4*>(
                                        &sh_p[1][1][rB][jB][0]))
                                   + sum4(*reinterpret_cast<const float4*>(
                                        &sh_p[2][1][rB][jB][0]));
                    const float xn = sum4(*reinterpret_cast<const float4*>(
                                        &sh_p[1][2][rB][jB][0]));
                    const float hn_ = sum4(*reinterpret_cast<const float4*>(
                                        &sh_p[2][2][rB][jB][0]));
                    const float rr = fsigmoid(ar);
                    const float zz = fsigmoid(az);
                    const float nn = ftanh(fmaf(rr, hn_, xn));
                    const float hp = sh_h2[par][rB * RS + hidx(jB)];
                    const float hv = fmaf(zz, hp - nn, nn);
                    sh_h2[par ^ 1][rB * RS + hidx(jB)] = hv;
                    outp[((size_t)(row4 + rB) * Tsz + tau) * Hs + jB] = hv;
                    if (tau == Tsz - 1)
                        finalp[(row4 + rB) * Hs + jB] = hv;
                }
            }
        } else if (xst && s + 1 < Tsz) {
            // stage x[s+1] into parity (s+1)&1
            sh_x[par ^ 1][xr][xc] =
                __ldg(&x[((size_t)(row4 + xr) * Tsz + (s + 1)) * 3 + xc]);
        }
        __syncthreads();
    }
}

// ---------------------------------------------------------------------------
extern "C" void kernel_launch(void* const* d_in, const int* in_sizes, int n_in,
                              void* d_out, int out_size)
{
    (void)in_sizes; (void)n_in; (void)out_size;
    const float* x     = (const float*)d_in[0];
    const float* W_ih0 = (const float*)d_in[1];
    const float* W_hh0 = (const float*)d_in[2];
    const float* b_ih0 = (const float*)d_in[3];
    const float* b_hh0 = (const float*)d_in[4];
    const float* W_ih1 = (const float*)d_in[5];
    const float* W_hh1 = (const float*)d_in[6];
    const float* b_ih1 = (const float*)d_in[7];
    const float* b_hh1 = (const float*)d_in[8];

    float* out    = (float*)d_out;
    float* finalh = out + (size_t)Bsz * Tsz * Hs;

    gru_fused<<<128, 768>>>(x, W_ih0, W_hh0, b_ih0, b_hh0,
                            W_ih1, W_hh1, b_ih1, b_hh1, out, finalh);
}

// round 9
// speedup vs baseline: 1.1417x; 1.0001x over previous
#include <cuda_runtime.h>
#include <cstddef>

namespace {
constexpr int Bsz = 512, Tsz = 1024, Hs = 64, R = 4;
}

using ull = unsigned long long;

__device__ __forceinline__ void unpack2(ull v, float& lo, float& hi) {
    asm("mov.b64 {%0,%1},%2;" : "=f"(lo), "=f"(hi) : "l"(v));
}
__device__ __forceinline__ ull ffma2(ull a, ull b, ull c) {
    ull d;
    asm("fma.rn.f32x2 %0,%1,%2,%3;" : "=l"(d) : "l"(a), "l"(b), "l"(c));
    return d;
}
__device__ __forceinline__ float fast_ex2(float x) {
    float r; asm("ex2.approx.f32 %0,%1;" : "=f"(r) : "f"(x)); return r;
}
__device__ __forceinline__ float fast_rcp(float x) {
    float r; asm("rcp.approx.f32 %0,%1;" : "=f"(r) : "f"(x)); return r;
}
__device__ __forceinline__ float fsigmoid(float x) {
    return fast_rcp(1.0f + fast_ex2(-1.44269504f * x));
}
__device__ __forceinline__ float ftanh(float x) {
    float ax = fabsf(x);
    float t  = fast_ex2(-2.88539008f * ax);          // exp(-2|x|)
    float y  = (1.0f - t) * fast_rcp(1.0f + t);
    return copysignf(y, x);
}

// ---------------------------------------------------------------------------
// Fused 2-layer GRU. Grid 128 x 384; CTA owns 4 batch rows.
// PHASE A: thread = (m = tx>>7, j = (tx&127)>>1, half = tx&1). Each thread
//   dots 3 gate-rows (j, j+64, j+128) of its matrix over a 32-k half against
//   4 rows (m=0: Whh0.h1[s-1], m=1: Wih1.h1[s-1], m=2: Whh1.h2[s-2]).
//   48 packed f32x2 weight regs -> 6 FFMA2 per LDS.128. NO shuffles: each
//   thread stores one float4 {pr,pz,pn,xn} per row to sh_p[m][r][j][half]
//   (contiguous 512B warp STS.128; BAR.SYNC drains STS). m=0 lanes also fold
//   the layer-0 x-projection: half0 contributes the biases, half1 the x-dot
//   (uniform code via per-lane constants -> no divergence).
// PHASE B: m=0 threads do TWO L0 combines (rows 2*half, 2*half+1; data
//   produced by their own warp): 2 LDS.128 + pairwise add + gates -> h1[s].
//   m=1 threads do L1 rows 0-1, m=2 rows 2-3: 4 LDS.128 + gates -> h2[s-1]
//   -> smem + global output. m=2 lanes 0..11 stage x[s+1]. 2 barriers/step.
// ---------------------------------------------------------------------------
__global__ void __launch_bounds__(384, 1) gru_fused(
    const float* __restrict__ x,
    const float* __restrict__ W_ih0, const float* __restrict__ W_hh0,
    const float* __restrict__ b_ih0, const float* __restrict__ b_hh0,
    const float* __restrict__ W_ih1, const float* __restrict__ W_hh1,
    const float* __restrict__ b_ih1, const float* __restrict__ b_hh1,
    float* __restrict__ outp,        // (B,T,64)
    float* __restrict__ finalp)      // (B,64)
{
    __shared__ float  sh_h1[2][R][2][36];   // [parity][row][khalf][32+pad]
    __shared__ float  sh_h2[2][R][2][36];
    __shared__ float4 sh_p [3][R][64][2];   // [matrix][row][j][half]
    __shared__ float  sh_x [2][R][3];       // staged x[t]

    const int tx   = threadIdx.x;
    const int m    = tx >> 7;            // 0: Whh0, 1: Wih1, 2: Whh1
    const int lr   = tx & 127;
    const int half = lr & 1;
    const int j    = lr >> 1;
    const int kb   = half * 32;

    // ---- phase-A weights: 3 gate-rows x 32-k half, packed f32x2 ----
    const float* __restrict__ Wm = (m == 0) ? W_hh0 : (m == 1) ? W_ih1 : W_hh1;
    ull w2[48];
    const ull* __restrict__ Wll = reinterpret_cast<const ull*>(Wm);
#pragma unroll
    for (int g3 = 0; g3 < 3; g3++) {
        const int g = j + g3 * 64;
#pragma unroll
        for (int kk = 0; kk < 16; kk++)
            w2[g3 * 16 + kk] = Wll[(g * 64 + kb) / 2 + kk];
    }

    // ---- per-lane fold constants ----
    // m=0: unified x-proj/bias: result += x2*c[g][2] + x1*c[g][1] + x0*c[g][0] + base[g]
    //      half0: c=0, base=bias;  half1: c=W_ih0 row, base=0.
    // m=1/m=2: plain bias adds (zero on half1).
    float cxr[3] = {0.f, 0.f, 0.f}, cxz[3] = {0.f, 0.f, 0.f}, cxn[3] = {0.f, 0.f, 0.f};
    float baseR = 0.f, baseZ = 0.f, baseN = 0.f, baseX = 0.f;  // baseX: xan slot
    if (m == 0) {
        if (half == 0) {
            baseR = b_ih0[j]       + b_hh0[j];
            baseZ = b_ih0[j + 64]  + b_hh0[j + 64];
            baseN = b_hh0[j + 128];              // recurrent n (inside r*)
            baseX = b_ih0[j + 128];              // input-side n bias
        } else {
#pragma unroll
            for (int c = 0; c < 3; c++) {
                cxr[c] = W_ih0[ j        * 3 + c];
                cxz[c] = W_ih0[(j + 64)  * 3 + c];
                cxn[c] = W_ih0[(j + 128) * 3 + c];
            }
        }
    } else if (m == 1) {
        if (half == 0) {
            baseR = b_ih1[j]       + b_hh1[j];
            baseZ = b_ih1[j + 64]  + b_hh1[j + 64];
            baseN = b_ih1[j + 128];              // input-side n
        }
    } else {
        if (half == 0) baseN = b_hh1[j + 128];   // recurrent n
    }

    // ---- phase-B task mapping ----
    // m=0: L0 rows {2*half, 2*half+1};  m=1: L1 row = half;  m=2: L1 row = 2+half
    const int rL1 = (m == 1) ? half : 2 + half;

    // x staging: m==2 lanes lr<12
    const bool xst = (m == 2) && (lr < 12);
    const int  xr  = xst ? lr / 3 : 0, xc = xst ? lr % 3 : 0;
    const int row4 = blockIdx.x * 4;

    // ---- init ----
    for (int i = tx; i < 2 * R * 2 * 36; i += 384) {
        reinterpret_cast<float*>(sh_h1)[i] = 0.f;
        reinterpret_cast<float*>(sh_h2)[i] = 0.f;
    }
    if (xst)
        sh_x[0][xr][xc] = __ldg(&x[((size_t)(row4 + xr) * Tsz) * 3 + xc]);
    __syncthreads();

    for (int s = 0; s <= Tsz; s++) {
        const int par = s & 1;

        // ===================== PHASE A ===================================
        const float* __restrict__ hsrc =
            (m == 2) ? &sh_h2[par][0][half][0] : &sh_h1[par][0][half][0];
#pragma unroll
        for (int r = 0; r < R; r++) {
            const ulonglong2* __restrict__ hb =
                reinterpret_cast<const ulonglong2*>(hsrc + r * 72);
            ull a0 = 0ull, a1 = 0ull, a2 = 0ull;
#pragma unroll
            for (int i = 0; i < 8; i++) {
                const ulonglong2 h4 = hb[i];               // LDS.128, 2 addrs
                a0 = ffma2(h4.x, w2[2 * i],          a0);
                a0 = ffma2(h4.y, w2[2 * i + 1],      a0);
                a1 = ffma2(h4.x, w2[16 + 2 * i],     a1);
                a1 = ffma2(h4.y, w2[16 + 2 * i + 1], a1);
                a2 = ffma2(h4.x, w2[32 + 2 * i],     a2);
                a2 = ffma2(h4.y, w2[32 + 2 * i + 1], a2);
            }
            float l, h;
            unpack2(a0, l, h); float pr = l + h;
            unpack2(a1, l, h); float pz = l + h;
            unpack2(a2, l, h); float pn = l + h;
            float xn4;
            if (m == 0) {
                const float x0 = sh_x[par][r][0];
                const float x1 = sh_x[par][r][1];
                const float x2 = sh_x[par][r][2];
                pr  = pr + fmaf(x2, cxr[2], fmaf(x1, cxr[1], fmaf(x0, cxr[0], baseR)));
                pz  = pz + fmaf(x2, cxz[2], fmaf(x1, cxz[1], fmaf(x0, cxz[0], baseZ)));
                pn  = pn + baseN;
                xn4 =      fmaf(x2, cxn[2], fmaf(x1, cxn[1], fmaf(x0, cxn[0], baseX)));
            } else {
                pr  = pr + baseR;
                pz  = pz + baseZ;
                pn  = pn + baseN;
                xn4 = 0.f;
            }
            sh_p[m][r][j][half] = make_float4(pr, pz, pn, xn4);   // STS.128
        }
        __syncthreads();                      // drains the STS above

        // ===================== PHASE B ===================================
        if (m == 0) {
            if (s < Tsz) {                    // two h1[s] combines
#pragma unroll
                for (int rr2 = 0; rr2 < 2; rr2++) {
                    const int rr = 2 * half + rr2;
                    const float4 pa = sh_p[0][rr][j][0];
                    const float4 pb = sh_p[0][rr][j][1];
                    const float ar  = pa.x + pb.x;
                    const float az  = pa.y + pb.y;
                    const float pn  = pa.z + pb.z;   // recurrent n (+bhh)
                    const float xan = pa.w + pb.w;   // input n (+bih)
                    const float rg = fsigmoid(ar);
                    const float zg = fsigmoid(az);
                    const float nn = ftanh(fmaf(rg, pn, xan));
                    const float hp = sh_h1[par][rr][j >> 5][j & 31];
                    sh_h1[par ^ 1][rr][j >> 5][j & 31] = fmaf(zg, hp - nn, nn);
                }
            }
        } else {
            if (s >= 1) {                     // h2[s-1] -> output
                const int tau = s - 1;
                const float4 qa = sh_p[1][rL1][j][0];
                const float4 qb = sh_p[1][rL1][j][1];
                const float4 ra = sh_p[2][rL1][j][0];
                const float4 rb = sh_p[2][rL1][j][1];
                const float ar  = (qa.x + qb.x) + (ra.x + rb.x);
                const float az  = (qa.y + qb.y) + (ra.y + rb.y);
                const float xan = qa.z + qb.z;   // input-side n (+bih)
                const float pnn = ra.z + rb.z;   // recurrent n (+bhh)
                const float rg = fsigmoid(ar);
                const float zg = fsigmoid(az);
                const float nn = ftanh(fmaf(rg, pnn, xan));
                const float hp = sh_h2[par][rL1][j >> 5][j & 31];
                const float hn = fmaf(zg, hp - nn, nn);
                sh_h2[par ^ 1][rL1][j >> 5][j & 31] = hn;
                outp[((size_t)(row4 + rL1) * Tsz + tau) * Hs + j] = hn;
                if (tau == Tsz - 1)
                    finalp[(row4 + rL1) * Hs + j] = hn;
            }
            if (xst && s + 1 < Tsz)           // stage x[s+1]
                sh_x[par ^ 1][xr][xc] =
                    __ldg(&x[((size_t)(row4 + xr) * Tsz + (s + 1)) * 3 + xc]);
        }
        __syncthreads();
    }
}

// ---------------------------------------------------------------------------
extern "C" void kernel_launch(void* const* d_in, const int* in_sizes, int n_in,
                              void* d_out, int out_size)
{
    (void)in_sizes; (void)n_in; (void)out_size;
    const float* x     = (const float*)d_in[0];
    const float* W_ih0 = (const float*)d_in[1];
    const float* W_hh0 = (const float*)d_in[2];
    const float* b_ih0 = (const float*)d_in[3];
    const float* b_hh0 = (const float*)d_in[4];
    const float* W_ih1 = (const float*)d_in[5];
    const float* W_hh1 = (const float*)d_in[6];
    const float* b_ih1 = (const float*)d_in[7];
    const float* b_hh1 = (const float*)d_in[8];

    float* out    = (float*)d_out;
    float* finalh = out + (size_t)Bsz * Tsz * Hs;

    gru_fused<<<128, 384>>>(x, W_ih0, W_hh0, b_ih0, b_hh0,
                            W_ih1, W_hh1, b_ih1, b_hh1, out, finalh);
}